// round 7
// baseline (speedup 1.0000x reference)
#include <cuda_runtime.h>
#include <stdint.h>

// N=100000, W=32, D=32. Output row = 1088 floats = 272 float4.
// Per row i: [ gathered x rows (256 f4) | dis (8 f4) | angle (8 f4) ]
// Warp handles TWO rows, processed back-to-back (16 payload regs live at
// once instead of 32) with a launch_bounds occupancy floor of 6 blocks/SM.

#define ROW_F4 272

__global__ __launch_bounds__(256, 6)
void fused_gather_concat_warp2i_kernel(const float4* __restrict__ x4,
                                       const void*  __restrict__ idx,
                                       const float4* __restrict__ dis4,
                                       const float4* __restrict__ ang4,
                                       float4* __restrict__ out4,
                                       int n_rows)
{
    const int warp_id = (blockIdx.x * blockDim.x + threadIdx.x) >> 5;
    const int lane    = threadIdx.x & 31;

    // Dtype detection (values < 100000: if little-endian int64, all odd
    // 32-bit words are 0; 32 random i32 all-zero: p ~ 1e-160). Same 256B
    // for every warp -> broadcast, negligible.
    const int probe = __ldg((const int*)idx + 2 * lane + 1);
    const bool is64 = (__ballot_sync(0xffffffffu, probe != 0) == 0u);

    const int i0 = warp_id * 2;
    if (i0 >= n_rows) return;

    const int wbase = lane >> 3;   // lane-group (0..3)
    const int seg   = lane & 7;    // float4 within the 32-float x row

#pragma unroll
    for (int rr = 0; rr < 2; rr++) {
        const int i = i0 + rr;
        if (i >= n_rows) break;

        // One idx element per lane (coalesced, read-once).
        int ji;
        if (is64) ji = (int)__ldcs((const long long*)idx + (long long)i * 32 + lane);
        else      ji = __ldcs((const int*)idx + i * 32 + lane);

        // Distribute the 8 needed neighbor indices via shuffle.
        int jw[8];
#pragma unroll
        for (int it = 0; it < 8; it++)
            jw[it] = __shfl_sync(0xffffffffu, ji, it * 4 + wbase);

        // 8 independent gathers (MLP=8 per row; 2 rows in flight via the
        // store/load overlap between iterations). .cg: skip L1 allocate.
        float4 v[8];
#pragma unroll
        for (int it = 0; it < 8; it++)
            v[it] = __ldcg(x4 + (long long)jw[it] * 8 + seg);

        // Coalesced streaming stores.
        float4* __restrict__ orow = out4 + (long long)i * ROW_F4;
#pragma unroll
        for (int it = 0; it < 8; it++)
            __stcs(orow + it * 32 + lane, v[it]);

        // Tail: dis (8 f4) | angle (8 f4), lanes 0..15.
        if (lane < 8)
            __stcs(orow + 256 + lane, __ldcs(dis4 + i * 8 + lane));
        else if (lane < 16)
            __stcs(orow + 256 + lane, __ldcs(ang4 + i * 8 + (lane - 8)));
    }
}

extern "C" void kernel_launch(void* const* d_in, const int* in_sizes, int n_in,
                              void* d_out, int out_size)
{
    const float4* x4   = (const float4*)d_in[0];
    const void*   idx  = d_in[1];
    const float4* dis4 = (const float4*)d_in[2];
    const float4* ang4 = (const float4*)d_in[3];
    float4* out4 = (float4*)d_out;

    const int n_rows = in_sizes[0] / 32;   // N

    const int threads = 256;                        // 8 warps/block
    const int rows_per_block = 16;                  // 2 rows per warp
    const int blocks = (n_rows + rows_per_block - 1) / rows_per_block;
    fused_gather_concat_warp2i_kernel<<<blocks, threads>>>(x4, idx, dis4, ang4,
                                                           out4, n_rows);
}

// round 8
// speedup vs baseline: 1.1096x; 1.1096x over previous
#include <cuda_runtime.h>
#include <stdint.h>

// N=100000, W=32, D=32. Output row = 1088 floats = 272 float4.
// Per row i: [ gathered x rows (256 f4) | dis (8 f4) | angle (8 f4) ]
// Warp handles TWO rows; ALL loads (2 idx, 16 gathers, tail) front-batched
// for max MLP, then all stores. At the LTS (~900MB L2 traffic) floor.

#define ROW_F4 272

__global__ __launch_bounds__(256)
void fused_gather_concat_warp2_kernel(const float4* __restrict__ x4,
                                      const void*  __restrict__ idx,
                                      const float4* __restrict__ dis4,
                                      const float4* __restrict__ ang4,
                                      float4* __restrict__ out4,
                                      int n_rows)
{
    const int warp_id = (blockIdx.x * blockDim.x + threadIdx.x) >> 5;
    const int lane    = threadIdx.x & 31;

    // Dtype detection (values < 100000: little-endian int64 => all odd
    // 32-bit words are 0; 32 random i32 all-zero: p ~ 1e-160). Broadcast.
    const int probe = __ldg((const int*)idx + 2 * lane + 1);
    const bool is64 = (__ballot_sync(0xffffffffu, probe != 0) == 0u);

    const int i0 = warp_id * 2;
    const int i1 = i0 + 1;
    if (i0 >= n_rows) return;
    const bool has1 = (i1 < n_rows);

    // idx loads: one element per lane per row (coalesced, read-once).
    int ja, jb = 0;
    if (is64) {
        ja = (int)__ldcs((const long long*)idx + (long long)i0 * 32 + lane);
        if (has1) jb = (int)__ldcs((const long long*)idx + (long long)i1 * 32 + lane);
    } else {
        ja = __ldcs((const int*)idx + i0 * 32 + lane);
        if (has1) jb = __ldcs((const int*)idx + i1 * 32 + lane);
    }

    // Tail payload (independent of idx): issue early so it rides the batch.
    float4 tv0, tv1;
    {
        const int li = (lane < 16) ? i0 : i1;
        const int lr = lane & 15;
        const bool lv = (lane < 16) || has1;
        if (lv) {
            if (lr < 8) tv0 = __ldcs(dis4 + li * 8 + lr);
            else        tv0 = __ldcs(ang4 + li * 8 + (lr - 8));
        }
        (void)tv1;
    }

    const int wbase = lane >> 3;   // lane-group (0..3)
    const int seg   = lane & 7;    // float4 within the 32-float x row

    // Distribute needed neighbor indices via shuffle.
    int jwa[8], jwb[8];
#pragma unroll
    for (int it = 0; it < 8; it++) {
        jwa[it] = __shfl_sync(0xffffffffu, ja, it * 4 + wbase);
        jwb[it] = __shfl_sync(0xffffffffu, jb, it * 4 + wbase);
    }

    // 16 independent gathers (MLP=16+tail). .cg: skip L1 allocate (random
    // 12.8MB working set cannot live in 228KB L1).
    float4 va[8], vb[8];
#pragma unroll
    for (int it = 0; it < 8; it++)
        va[it] = __ldcg(x4 + (long long)jwa[it] * 8 + seg);
    if (has1) {
#pragma unroll
        for (int it = 0; it < 8; it++)
            vb[it] = __ldcg(x4 + (long long)jwb[it] * 8 + seg);
    }

    // Coalesced streaming stores (output never re-read).
    float4* __restrict__ orow0 = out4 + (long long)i0 * ROW_F4;
#pragma unroll
    for (int it = 0; it < 8; it++)
        __stcs(orow0 + it * 32 + lane, va[it]);
    if (has1) {
        float4* __restrict__ orow1 = out4 + (long long)i1 * ROW_F4;
#pragma unroll
        for (int it = 0; it < 8; it++)
            __stcs(orow1 + it * 32 + lane, vb[it]);

        // Packed tail store: lanes 0-15 -> row0, lanes 16-31 -> row1.
        if (lane < 16) __stcs(orow0 + 256 + lane, tv0);
        else           __stcs(orow1 + 256 + (lane - 16), tv0);
    } else {
        if (lane < 16) __stcs(orow0 + 256 + lane, tv0);
    }
}

extern "C" void kernel_launch(void* const* d_in, const int* in_sizes, int n_in,
                              void* d_out, int out_size)
{
    const float4* x4   = (const float4*)d_in[0];
    const void*   idx  = d_in[1];
    const float4* dis4 = (const float4*)d_in[2];
    const float4* ang4 = (const float4*)d_in[3];
    float4* out4 = (float4*)d_out;

    const int n_rows = in_sizes[0] / 32;   // N

    const int threads = 256;                        // 8 warps/block
    const int rows_per_block = 16;                  // 2 rows per warp
    const int blocks = (n_rows + rows_per_block - 1) / rows_per_block;
    fused_gather_concat_warp2_kernel<<<blocks, threads>>>(x4, idx, dis4, ang4,
                                                          out4, n_rows);
}